// round 11
// baseline (speedup 1.0000x reference)
#include <cuda_runtime.h>
#include <cuda_fp16.h>
#include <cstdint>

// QConv1d via mma.sync f16 m16n8k16 implicit GEMM, 2 independent CTAs/SM:
// half-size tiles so two CTAs co-reside; one CTA's serialized fill/barrier
// phases overlap the other CTA's MMA stream.
//
// out[n,o,l] = 0.125 * sum_{c,k} x[n,c,l+k-4] * w[o,c,k] + bias[o]
// GEMM: M = 128 l per tile, N = 64 (o), K = 576; k-step = 16 ch x 1 tap.
// x stored channel-pair interleaved fp16x2 -> A fragment = 1 aligned 32-bit
// conflict-free LDS (stride 136 words = 8 mod 32). B pre-packed in fragment
// order once per persistent CTA. 256 threads = 8 warps, warp grid 4(M) x 2(N).

#define N_BATCH 8
#define C_IN    64
#define L_IN    16384
#define O_OUT   64
#define KSZ     9
#define PADK    4
#define SCALEF  0.125f

#define THREADS 256
#define TILE_L  128
#define TPERN   (L_IN / TILE_L)               // 128
#define NTILES  (N_BATCH * TPERN)             // 1024
#define GRID    296                           // 2 persistent CTAs per SM

#define KTOT    (C_IN * KSZ)                  // 576
#define NSTEPS  36                            // 9 taps x 4 channel-groups, K=16 each

#define XS2_STRIDE 136                        // fp16x2 words per row; 136 % 32 == 8
#define XS2_ROWB   (XS2_STRIDE * 4)           // 544 bytes
#define XS2_WORDS  (32 * XS2_STRIDE)          // 4352

// SMEM layout (bytes)
#define PK_BYTES   (NSTEPS * 256 * 8)         // 73728
#define SM_PK      0
#define SM_XS      PK_BYTES
#define SM_BIAS    (SM_XS + XS2_WORDS * 4)    // 91136
#define SM_TOTAL   (SM_BIAS + O_OUT * 4)      // 91392 (x2 = 178.5 KB/SM)

__device__ __forceinline__ uint32_t smem_u32(const void* p) {
    uint32_t a;
    asm("{ .reg .u64 t; cvta.to.shared.u64 t, %1; cvt.u32.u64 %0, t; }" : "=r"(a) : "l"(p));
    return a;
}

__device__ __forceinline__ uint32_t lds_b32(uint32_t a) {
    uint32_t v;
    asm volatile("ld.shared.b32 %0, [%1];" : "=r"(v) : "r"(a));
    return v;
}

__device__ __forceinline__ void lds_v2(uint32_t a, uint32_t& v0, uint32_t& v1) {
    asm volatile("ld.shared.v2.b32 {%0, %1}, [%2];" : "=r"(v0), "=r"(v1) : "r"(a));
}

__device__ __forceinline__ uint32_t packh2(float a, float b) {
    __half2 h = __floats2half2_rn(a, b);      // low = a, high = b
    return *reinterpret_cast<uint32_t*>(&h);
}

__device__ __forceinline__ void mma_f16(float* c, const uint32_t* a, uint32_t b0, uint32_t b1) {
    asm volatile(
        "mma.sync.aligned.m16n8k16.row.col.f32.f16.f16.f32 "
        "{%0,%1,%2,%3}, {%4,%5,%6,%7}, {%8,%9}, {%0,%1,%2,%3};"
        : "+f"(c[0]), "+f"(c[1]), "+f"(c[2]), "+f"(c[3])
        : "r"(a[0]), "r"(a[1]), "r"(a[2]), "r"(a[3]), "r"(b0), "r"(b1));
}

__global__ void __launch_bounds__(THREADS, 2)
qconv1d_mma(const float* __restrict__ x, const float* __restrict__ w,
            const float* __restrict__ bias, float* __restrict__ out)
{
    extern __shared__ char smem[];
    uint32_t* xs2     = (uint32_t*)(smem + SM_XS);
    float*    bias_sm = (float*)(smem + SM_BIAS);

    const int tid  = threadIdx.x;
    const int wid  = tid >> 5;
    const int lane = tid & 31;
    const int mBlk = wid & 3;        // M block: rows [mBlk*32, +32) of 128
    const int nBlk = wid >> 2;       // N block: cols [nBlk*32, +32) of 64
    const int g    = lane >> 2;      // group id 0..7
    const int tig  = lane & 3;       // thread in group

    // ---- pack weights in f16 fragment order (once per persistent CTA) ----
    // uint2 index: s*256 + nB*128 + nt*32 + lane, s = a*4 + cg
    {
        uint2* pk = (uint2*)(smem + SM_PK);
        for (int i = tid; i < NSTEPS * 256; i += THREADS) {
            int li = i & 31;
            int nt = (i >> 5) & 3;
            int nB = (i >> 7) & 1;
            int s  = i >> 8;
            int a  = s >> 2;
            int cg = s & 3;
            int o  = nB * 32 + nt * 8 + (li >> 2);
            int c0 = cg * 16 + 2 * (li & 3);
            const float* wr = w + o * KTOT + a;
            uint2 v;
            v.x = packh2(wr[c0 * KSZ],       wr[(c0 + 1) * KSZ]);
            v.y = packh2(wr[(c0 + 8) * KSZ], wr[(c0 + 9) * KSZ]);
            pk[i] = v;
        }
        if (tid < O_OUT) bias_sm[tid] = bias[tid];
    }

    const uint32_t sbase = smem_u32(smem);
    // A base: channel-pair row tig (within cg block of 8 rows), m word (mBlk*32+g)
    const uint32_t xsA = sbase + SM_XS + (uint32_t)tig * XS2_ROWB + (uint32_t)(mBlk * 32 + g) * 4;
    const uint32_t pkB = sbase + SM_PK + (uint32_t)(nBlk * 128 + lane) * 8;

    for (int t = blockIdx.x; t < NTILES; t += GRID) {
        const int n     = t / TPERN;
        const int tileL = (t % TPERN) * TILE_L;
        const float* xn = x + (size_t)n * C_IN * L_IN;

        // ---- fill xs2 [32 cp][136 l-words], l = tileL-4+j, fp16x2, zero-padded ----
        for (int i = tid; i < XS2_WORDS; i += THREADS) {
            int cp = i / XS2_STRIDE;
            int j  = i - cp * XS2_STRIDE;
            int gl = tileL - PADK + j;
            float v0 = 0.0f, v1 = 0.0f;
            if (gl >= 0 && gl < L_IN) {
                const float* xr = xn + (size_t)(2 * cp) * L_IN + gl;
                v0 = xr[0];
                v1 = xr[L_IN];
            }
            xs2[i] = packh2(v0, v1);
        }
        __syncthreads();

        float acc[2][4][4];
        #pragma unroll
        for (int mt = 0; mt < 2; ++mt)
            #pragma unroll
            for (int nt = 0; nt < 4; ++nt)
                #pragma unroll
                for (int r = 0; r < 4; ++r) acc[mt][nt][r] = 0.0f;

        #pragma unroll 1
        for (int a = 0; a < KSZ; ++a) {            // tap
            const uint32_t pAa = xsA + (uint32_t)a * 4;
            const uint32_t pBa = pkB + (uint32_t)a * (4 * 2048);
            #pragma unroll
            for (int cg = 0; cg < 4; ++cg) {       // 16-channel group
                const uint32_t pA = pAa + (uint32_t)cg * (8 * XS2_ROWB);
                uint32_t af[2][4];
                #pragma unroll
                for (int mt = 0; mt < 2; ++mt) {
                    const uint32_t p = pA + mt * 64;
                    af[mt][0] = lds_b32(p);
                    af[mt][1] = lds_b32(p + 32);
                    af[mt][2] = lds_b32(p + 4 * XS2_ROWB);
                    af[mt][3] = lds_b32(p + 4 * XS2_ROWB + 32);
                }
                uint32_t bf[4][2];
                #pragma unroll
                for (int nt = 0; nt < 4; ++nt)
                    lds_v2(pBa + cg * 2048 + nt * 256, bf[nt][0], bf[nt][1]);
                #pragma unroll
                for (int nt = 0; nt < 4; ++nt) {
                    mma_f16(acc[0][nt], af[0], bf[nt][0], bf[nt][1]);
                    mma_f16(acc[1][nt], af[1], bf[nt][0], bf[nt][1]);
                }
            }
        }
        __syncthreads();   // all warps done reading xs2 before next tile refill

        // ---- epilogue: scale + bias, direct stores ----
        float* ob = out + (size_t)n * O_OUT * L_IN + tileL;
        #pragma unroll
        for (int mt = 0; mt < 2; ++mt) {
            const int r0 = mBlk * 32 + mt * 16 + g;
            #pragma unroll
            for (int nt = 0; nt < 4; ++nt) {
                const int o0 = nBlk * 32 + nt * 8 + tig * 2;
                const float b0 = bias_sm[o0], b1 = bias_sm[o0 + 1];
                ob[(size_t)o0 * L_IN + r0]           = acc[mt][nt][0] * SCALEF + b0;
                ob[(size_t)(o0 + 1) * L_IN + r0]     = acc[mt][nt][1] * SCALEF + b1;
                ob[(size_t)o0 * L_IN + r0 + 8]       = acc[mt][nt][2] * SCALEF + b0;
                ob[(size_t)(o0 + 1) * L_IN + r0 + 8] = acc[mt][nt][3] * SCALEF + b1;
            }
        }
    }
}

extern "C" void kernel_launch(void* const* d_in, const int* in_sizes, int n_in,
                              void* d_out, int out_size)
{
    const float* x    = (const float*)d_in[0];
    const float* w    = (const float*)d_in[1];
    const float* bias = (const float*)d_in[2];
    float* out        = (float*)d_out;

    cudaFuncSetAttribute(qconv1d_mma,
                         cudaFuncAttributeMaxDynamicSharedMemorySize, SM_TOTAL);
    qconv1d_mma<<<GRID, THREADS, SM_TOTAL>>>(x, w, bias, out);
}

// round 12
// speedup vs baseline: 1.2804x; 1.2804x over previous
#include <cuda_runtime.h>
#include <cuda_fp16.h>
#include <cstdint>

// QConv1d via mma.sync f16 m16n8k16 implicit GEMM with split-phase prefetch:
// next tile's x is LDG'd into registers early (hidden under MMA taps) and
// STS'd into a double buffer late, removing the serialized fill stall.
//
// out[n,o,l] = 0.125 * sum_{c,k} x[n,c,l+k-4] * w[o,c,k] + bias[o]
// GEMM: M = 256 l per tile, N = 64 (o), K = 576; k-step = 16 ch x 1 tap.
// x stored channel-pair interleaved fp16x2 -> A fragment = 1 aligned 32-bit
// conflict-free LDS. B pre-packed in fragment order once per persistent CTA.
// 512 threads = 16 warps, warp grid 8(M) x 2(N), 32x32 C per warp, 1 CTA/SM.

#define N_BATCH 8
#define C_IN    64
#define L_IN    16384
#define O_OUT   64
#define KSZ     9
#define PADK    4
#define SCALEF  0.125f

#define THREADS 512
#define TILE_L  256
#define TPERN   (L_IN / TILE_L)               // 64
#define NTILES  (N_BATCH * TPERN)             // 512
#define GRID    148

#define KTOT    (C_IN * KSZ)                  // 576
#define NSTEPS  36

#define XS2_STRIDE 264                        // fp16x2 words per row; 264 % 32 == 8
#define XS2_ROWB   (XS2_STRIDE * 4)           // 1056 bytes
#define XS2_WORDS  (32 * XS2_STRIDE)          // 8448 words per buffer
#define XS2_BYTES  (XS2_WORDS * 4)            // 33792

// prefetch chunking: 8448 = 16*512 + 256
#define CH0_K 8                               // words tid + k*512, k in [0,8)
#define CH1_K 9                               // k in [8,17); k==16 only tid<256

// SMEM layout (bytes)
#define PK_BYTES   (NSTEPS * 256 * 8)         // 73728
#define SM_PK      0
#define SM_XS      PK_BYTES                   // double buffer
#define SM_BIAS    (SM_XS + 2 * XS2_BYTES)    // 141312
#define SM_TOTAL   (SM_BIAS + O_OUT * 4)      // 141568

__device__ __forceinline__ uint32_t smem_u32(const void* p) {
    uint32_t a;
    asm("{ .reg .u64 t; cvta.to.shared.u64 t, %1; cvt.u32.u64 %0, t; }" : "=r"(a) : "l"(p));
    return a;
}

__device__ __forceinline__ uint32_t lds_b32(uint32_t a) {
    uint32_t v;
    asm volatile("ld.shared.b32 %0, [%1];" : "=r"(v) : "r"(a));
    return v;
}

__device__ __forceinline__ void lds_v2(uint32_t a, uint32_t& v0, uint32_t& v1) {
    asm volatile("ld.shared.v2.b32 {%0, %1}, [%2];" : "=r"(v0), "=r"(v1) : "r"(a));
}

__device__ __forceinline__ uint32_t packh2(float a, float b) {
    __half2 h = __floats2half2_rn(a, b);      // low = a, high = b
    return *reinterpret_cast<uint32_t*>(&h);
}

__device__ __forceinline__ void mma_f16(float* c, const uint32_t* a, uint32_t b0, uint32_t b1) {
    asm volatile(
        "mma.sync.aligned.m16n8k16.row.col.f32.f16.f16.f32 "
        "{%0,%1,%2,%3}, {%4,%5,%6,%7}, {%8,%9}, {%0,%1,%2,%3};"
        : "+f"(c[0]), "+f"(c[1]), "+f"(c[2]), "+f"(c[3])
        : "r"(a[0]), "r"(a[1]), "r"(a[2]), "r"(a[3]), "r"(b0), "r"(b1));
}

__global__ void __launch_bounds__(THREADS, 1)
qconv1d_mma(const float* __restrict__ x, const float* __restrict__ w,
            const float* __restrict__ bias, float* __restrict__ out)
{
    extern __shared__ char smem[];
    float* bias_sm = (float*)(smem + SM_BIAS);

    const int tid  = threadIdx.x;
    const int wid  = tid >> 5;
    const int lane = tid & 31;
    const int mBlk = wid & 7;        // M block: rows [mBlk*32, +32) of 256
    const int nBlk = wid >> 3;       // N block: cols [nBlk*32, +32) of 64
    const int g    = lane >> 2;      // group id 0..7
    const int tig  = lane & 3;       // thread in group

    // ---- pack weights in f16 fragment order (once per persistent CTA) ----
    {
        uint2* pk = (uint2*)(smem + SM_PK);
        for (int i = tid; i < NSTEPS * 256; i += THREADS) {
            int li = i & 31;
            int nt = (i >> 5) & 3;
            int nB = (i >> 7) & 1;
            int s  = i >> 8;
            int a  = s >> 2;
            int cg = s & 3;
            int o  = nB * 32 + nt * 8 + (li >> 2);
            int c0 = cg * 16 + 2 * (li & 3);
            const float* wr = w + o * KTOT + a;
            uint2 v;
            v.x = packh2(wr[c0 * KSZ],       wr[(c0 + 1) * KSZ]);
            v.y = packh2(wr[(c0 + 8) * KSZ], wr[(c0 + 9) * KSZ]);
            pk[i] = v;
        }
        if (tid < O_OUT) bias_sm[tid] = bias[tid];
    }

    const uint32_t sbase = smem_u32(smem);
    const uint32_t xsOff = (uint32_t)tig * XS2_ROWB + (uint32_t)(mBlk * 32 + g) * 4;
    const uint32_t pkB   = sbase + SM_PK + (uint32_t)(nBlk * 128 + lane) * 8;

    // ---- prologue: plain fill of buffer 0 with the first tile ----
    {
        const int t0 = blockIdx.x;       // < NTILES always (148 <= 512)
        uint32_t* dst = (uint32_t*)(smem + SM_XS);
        const int n     = t0 / TPERN;
        const int tileL = (t0 % TPERN) * TILE_L;
        const float* xn = x + (size_t)n * C_IN * L_IN;
        for (int i = tid; i < XS2_WORDS; i += THREADS) {
            int cp = i / XS2_STRIDE;
            int j  = i - cp * XS2_STRIDE;
            int gl = tileL - PADK + j;
            float v0 = 0.0f, v1 = 0.0f;
            if (gl >= 0 && gl < L_IN) {
                const float* xr = xn + (size_t)(2 * cp) * L_IN + gl;
                v0 = xr[0];
                v1 = xr[L_IN];
            }
            dst[i] = packh2(v0, v1);
        }
    }
    __syncthreads();

    int buf = 0;
    for (int t = blockIdx.x; t < NTILES; t += GRID) {
        const int n     = t / TPERN;
        const int tileL = (t % TPERN) * TILE_L;

        const int tn = t + GRID;
        const bool haveNext = (tn < NTILES);
        const float* xnn = x + (size_t)((haveNext ? tn : t) / TPERN) * C_IN * L_IN;
        const int tileLn = ((haveNext ? tn : t) % TPERN) * TILE_L;
        uint32_t* nxt = (uint32_t*)(smem + SM_XS + (buf ^ 1) * XS2_BYTES);

        const uint32_t xsA = sbase + SM_XS + (uint32_t)buf * XS2_BYTES + xsOff;

        float acc[2][4][4];
        #pragma unroll
        for (int mt = 0; mt < 2; ++mt)
            #pragma unroll
            for (int nt = 0; nt < 4; ++nt)
                #pragma unroll
                for (int r = 0; r < 4; ++r) acc[mt][nt][r] = 0.0f;

        // ---- prefetch chunk 0 (next tile) into registers: non-blocking LDGs ----
        float p0[CH0_K], p1[CH0_K];
        #pragma unroll
        for (int k = 0; k < CH0_K; ++k) {
            int i  = tid + k * THREADS;
            int cp = i / XS2_STRIDE;
            int j  = i - cp * XS2_STRIDE;
            int gl = tileLn - PADK + j;
            bool ok = haveNext && (gl >= 0) && (gl < L_IN);
            const float* xr = xnn + (size_t)(2 * cp) * L_IN + gl;
            p0[k] = ok ? xr[0]    : 0.0f;
            p1[k] = ok ? xr[L_IN] : 0.0f;
        }

        float q0[CH1_K], q1[CH1_K];

        #pragma unroll 1
        for (int a = 0; a < KSZ; ++a) {            // tap
            const uint32_t pAa = xsA + (uint32_t)a * 4;
            const uint32_t pBa = pkB + (uint32_t)a * (4 * 2048);
            #pragma unroll
            for (int cg = 0; cg < 4; ++cg) {       // 16-channel group
                const uint32_t pA = pAa + (uint32_t)cg * (8 * XS2_ROWB);
                uint32_t af[2][4];
                #pragma unroll
                for (int mt = 0; mt < 2; ++mt) {
                    const uint32_t p = pA + mt * 64;
                    af[mt][0] = lds_b32(p);
                    af[mt][1] = lds_b32(p + 32);
                    af[mt][2] = lds_b32(p + 4 * XS2_ROWB);
                    af[mt][3] = lds_b32(p + 4 * XS2_ROWB + 32);
                }
                uint32_t bf[4][2];
                #pragma unroll
                for (int nt = 0; nt < 4; ++nt)
                    lds_v2(pBa + cg * 2048 + nt * 256, bf[nt][0], bf[nt][1]);
                #pragma unroll
                for (int nt = 0; nt < 4; ++nt) {
                    mma_f16(acc[0][nt], af[0], bf[nt][0], bf[nt][1]);
                    mma_f16(acc[1][nt], af[1], bf[nt][0], bf[nt][1]);
                }
            }

            if (a == 3) {
                // LDG long done: commit chunk 0 to smem, then prefetch chunk 1
                if (haveNext) {
                    #pragma unroll
                    for (int k = 0; k < CH0_K; ++k)
                        nxt[tid + k * THREADS] = packh2(p0[k], p1[k]);
                }
                #pragma unroll
                for (int k = 0; k < CH1_K; ++k) {
                    int i = tid + (CH0_K + k) * THREADS;
                    bool inb = (i < XS2_WORDS);
                    int ii = inb ? i : 0;
                    int cp = ii / XS2_STRIDE;
                    int j  = ii - cp * XS2_STRIDE;
                    int gl = tileLn - PADK + j;
                    bool ok = haveNext && inb && (gl >= 0) && (gl < L_IN);
                    const float* xr = xnn + (size_t)(2 * cp) * L_IN + gl;
                    q0[k] = ok ? xr[0]    : 0.0f;
                    q1[k] = ok ? xr[L_IN] : 0.0f;
                }
            }
        }

        // ---- commit chunk 1 ----
        if (haveNext) {
            #pragma unroll
            for (int k = 0; k < CH1_K; ++k) {
                int i = tid + (CH0_K + k) * THREADS;
                if (i < XS2_WORDS)
                    nxt[i] = packh2(q0[k], q1[k]);
            }
        }

        // ---- epilogue: scale + bias, direct stores ----
        float* ob = out + (size_t)n * O_OUT * L_IN + tileL;
        #pragma unroll
        for (int mt = 0; mt < 2; ++mt) {
            const int r0 = mBlk * 32 + mt * 16 + g;
            #pragma unroll
            for (int nt = 0; nt < 4; ++nt) {
                const int o0 = nBlk * 32 + nt * 8 + tig * 2;
                const float b0 = bias_sm[o0], b1 = bias_sm[o0 + 1];
                ob[(size_t)o0 * L_IN + r0]           = acc[mt][nt][0] * SCALEF + b0;
                ob[(size_t)(o0 + 1) * L_IN + r0]     = acc[mt][nt][1] * SCALEF + b1;
                ob[(size_t)o0 * L_IN + r0 + 8]       = acc[mt][nt][2] * SCALEF + b0;
                ob[(size_t)(o0 + 1) * L_IN + r0 + 8] = acc[mt][nt][3] * SCALEF + b1;
            }
        }

        __syncthreads();   // next buffer visible to all; current buffer reads done
        buf ^= 1;
    }
}

extern "C" void kernel_launch(void* const* d_in, const int* in_sizes, int n_in,
                              void* d_out, int out_size)
{
    const float* x    = (const float*)d_in[0];
    const float* w    = (const float*)d_in[1];
    const float* bias = (const float*)d_in[2];
    float* out        = (float*)d_out;

    cudaFuncSetAttribute(qconv1d_mma,
                         cudaFuncAttributeMaxDynamicSharedMemorySize, SM_TOTAL);
    qconv1d_mma<<<GRID, THREADS, SM_TOTAL>>>(x, w, bias, out);
}

// round 13
// speedup vs baseline: 1.4494x; 1.1320x over previous
#include <cuda_runtime.h>
#include <cuda_fp16.h>
#include <cstdint>

// QConv1d via mma.sync f16 m16n8k16 implicit GEMM (R7 champion config) with a
// 4x-vectorized fill: interior of the x tile loaded as float4 (LDG.128) from
// two channel rows, packed to fp16x2, stored with one STS.128 — ~3x fewer
// fill instructions. Halo (8 words) handled scalar with bounds checks.
//
// out[n,o,l] = 0.125 * sum_{c,k} x[n,c,l+k-4] * w[o,c,k] + bias[o]
// GEMM: M = 256 l per tile, N = 64 (o), K = 576; k-step = 16 ch x 1 tap.
// x stored channel-pair interleaved fp16x2 -> A fragment = 1 aligned 32-bit
// conflict-free LDS. B pre-packed in fragment order once per persistent CTA.
// 512 threads = 16 warps, warp grid 8(M) x 2(N), 32x32 C per warp, 1 CTA/SM.

#define N_BATCH 8
#define C_IN    64
#define L_IN    16384
#define O_OUT   64
#define KSZ     9
#define PADK    4
#define SCALEF  0.125f

#define THREADS 512
#define TILE_L  256
#define TPERN   (L_IN / TILE_L)               // 64
#define NTILES  (N_BATCH * TPERN)             // 512
#define GRID    148

#define KTOT    (C_IN * KSZ)                  // 576
#define NSTEPS  36                            // 9 taps x 4 channel-groups, K=16 each

#define XS2_STRIDE 264                        // fp16x2 words per row; 264 % 32 == 8
#define XS2_ROWB   (XS2_STRIDE * 4)           // 1056 bytes
#define XS2_WORDS  (32 * XS2_STRIDE)          // 8448

// SMEM layout (bytes)
#define PK_BYTES   (NSTEPS * 256 * 8)         // 73728
#define SM_PK      0
#define SM_XS      PK_BYTES
#define SM_BIAS    (SM_XS + XS2_WORDS * 4)    // 107520
#define SM_TOTAL   (SM_BIAS + O_OUT * 4)      // 107776

__device__ __forceinline__ uint32_t smem_u32(const void* p) {
    uint32_t a;
    asm("{ .reg .u64 t; cvta.to.shared.u64 t, %1; cvt.u32.u64 %0, t; }" : "=r"(a) : "l"(p));
    return a;
}

__device__ __forceinline__ uint32_t lds_b32(uint32_t a) {
    uint32_t v;
    asm volatile("ld.shared.b32 %0, [%1];" : "=r"(v) : "r"(a));
    return v;
}

__device__ __forceinline__ void lds_v2(uint32_t a, uint32_t& v0, uint32_t& v1) {
    asm volatile("ld.shared.v2.b32 {%0, %1}, [%2];" : "=r"(v0), "=r"(v1) : "r"(a));
}

__device__ __forceinline__ uint32_t packh2(float a, float b) {
    __half2 h = __floats2half2_rn(a, b);      // low = a, high = b
    return *reinterpret_cast<uint32_t*>(&h);
}

__device__ __forceinline__ void mma_f16(float* c, const uint32_t* a, uint32_t b0, uint32_t b1) {
    asm volatile(
        "mma.sync.aligned.m16n8k16.row.col.f32.f16.f16.f32 "
        "{%0,%1,%2,%3}, {%4,%5,%6,%7}, {%8,%9}, {%0,%1,%2,%3};"
        : "+f"(c[0]), "+f"(c[1]), "+f"(c[2]), "+f"(c[3])
        : "r"(a[0]), "r"(a[1]), "r"(a[2]), "r"(a[3]), "r"(b0), "r"(b1));
}

__global__ void __launch_bounds__(THREADS, 1)
qconv1d_mma(const float* __restrict__ x, const float* __restrict__ w,
            const float* __restrict__ bias, float* __restrict__ out)
{
    extern __shared__ char smem[];
    uint32_t* xs2     = (uint32_t*)(smem + SM_XS);
    float*    bias_sm = (float*)(smem + SM_BIAS);

    const int tid  = threadIdx.x;
    const int wid  = tid >> 5;
    const int lane = tid & 31;
    const int mBlk = wid & 7;        // M block: rows [mBlk*32, +32) of 256
    const int nBlk = wid >> 3;       // N block: cols [nBlk*32, +32) of 64
    const int g    = lane >> 2;      // group id 0..7
    const int tig  = lane & 3;       // thread in group

    // ---- pack weights in f16 fragment order (once per persistent CTA) ----
    // uint2 index: s*256 + nB*128 + nt*32 + lane, s = a*4 + cg
    {
        uint2* pk = (uint2*)(smem + SM_PK);
        for (int i = tid; i < NSTEPS * 256; i += THREADS) {
            int li = i & 31;
            int nt = (i >> 5) & 3;
            int nB = (i >> 7) & 1;
            int s  = i >> 8;
            int a  = s >> 2;
            int cg = s & 3;
            int o  = nB * 32 + nt * 8 + (li >> 2);
            int c0 = cg * 16 + 2 * (li & 3);
            const float* wr = w + o * KTOT + a;
            uint2 v;
            v.x = packh2(wr[c0 * KSZ],       wr[(c0 + 1) * KSZ]);
            v.y = packh2(wr[(c0 + 8) * KSZ], wr[(c0 + 9) * KSZ]);
            pk[i] = v;
        }
        if (tid < O_OUT) bias_sm[tid] = bias[tid];
    }

    const uint32_t sbase = smem_u32(smem);
    // A base: channel-pair row tig (within cg block of 8 rows), m word (mBlk*32+g)
    const uint32_t xsA = sbase + SM_XS + (uint32_t)tig * XS2_ROWB + (uint32_t)(mBlk * 32 + g) * 4;
    const uint32_t pkB = sbase + SM_PK + (uint32_t)(nBlk * 128 + lane) * 8;

    for (int t = blockIdx.x; t < NTILES; t += GRID) {
        const int n     = t / TPERN;
        const int tileL = (t % TPERN) * TILE_L;
        const float* xn = x + (size_t)n * C_IN * L_IN;

        // ---- vectorized fill: interior [tileL, tileL+256) via float4 + STS.128 ----
        // quad q: cp = q>>6, qq = q&63 -> l = tileL + qq*4, words j = 4+qq*4..+3
        #pragma unroll
        for (int q = tid, it = 0; it < 4; q += THREADS, ++it) {
            const int cp = q >> 6;
            const int qq = q & 63;
            const float* r0 = xn + (size_t)(2 * cp) * L_IN + tileL + qq * 4;
            const float4 a4 = *(const float4*)r0;
            const float4 b4 = *(const float4*)(r0 + L_IN);
            uint4 v;
            v.x = packh2(a4.x, b4.x);
            v.y = packh2(a4.y, b4.y);
            v.z = packh2(a4.z, b4.z);
            v.w = packh2(a4.w, b4.w);
            *(uint4*)(xs2 + cp * XS2_STRIDE + 4 + qq * 4) = v;
        }
        // halo: 8 words per cp (j = 0..3 and 260..263), 256 threads, scalar + bounds
        if (tid < 256) {
            const int cp = tid >> 3;
            const int e  = tid & 7;
            const int j  = (e < 4) ? e : (256 + e);   // 0..3 or 260..263
            const int gl = tileL - PADK + j;
            float v0 = 0.0f, v1 = 0.0f;
            if (gl >= 0 && gl < L_IN) {
                const float* xr = xn + (size_t)(2 * cp) * L_IN + gl;
                v0 = xr[0];
                v1 = xr[L_IN];
            }
            xs2[cp * XS2_STRIDE + j] = packh2(v0, v1);
        }
        __syncthreads();

        float acc[2][4][4];
        #pragma unroll
        for (int mt = 0; mt < 2; ++mt)
            #pragma unroll
            for (int nt = 0; nt < 4; ++nt)
                #pragma unroll
                for (int r = 0; r < 4; ++r) acc[mt][nt][r] = 0.0f;

        #pragma unroll 1
        for (int a = 0; a < KSZ; ++a) {            // tap
            const uint32_t pAa = xsA + (uint32_t)a * 4;
            const uint32_t pBa = pkB + (uint32_t)a * (4 * 2048);
            #pragma unroll
            for (int cg = 0; cg < 4; ++cg) {       // 16-channel group
                const uint32_t pA = pAa + (uint32_t)cg * (8 * XS2_ROWB);
                uint32_t af[2][4];
                #pragma unroll
                for (int mt = 0; mt < 2; ++mt) {
                    const uint32_t p = pA + mt * 64;
                    af[mt][0] = lds_b32(p);
                    af[mt][1] = lds_b32(p + 32);
                    af[mt][2] = lds_b32(p + 4 * XS2_ROWB);
                    af[mt][3] = lds_b32(p + 4 * XS2_ROWB + 32);
                }
                uint32_t bf[4][2];
                #pragma unroll
                for (int nt = 0; nt < 4; ++nt)
                    lds_v2(pBa + cg * 2048 + nt * 256, bf[nt][0], bf[nt][1]);
                #pragma unroll
                for (int nt = 0; nt < 4; ++nt) {
                    mma_f16(acc[0][nt], af[0], bf[nt][0], bf[nt][1]);
                    mma_f16(acc[1][nt], af[1], bf[nt][0], bf[nt][1]);
                }
            }
        }
        __syncthreads();   // all warps done reading xs2 before next tile refill

        // ---- epilogue: scale + bias, direct stores ----
        float* ob = out + (size_t)n * O_OUT * L_IN + tileL;
        #pragma unroll
        for (int mt = 0; mt < 2; ++mt) {
            const int r0 = mBlk * 32 + mt * 16 + g;
            #pragma unroll
            for (int nt = 0; nt < 4; ++nt) {
                const int o0 = nBlk * 32 + nt * 8 + tig * 2;
                const float b0 = bias_sm[o0], b1 = bias_sm[o0 + 1];
                ob[(size_t)o0 * L_IN + r0]           = acc[mt][nt][0] * SCALEF + b0;
                ob[(size_t)(o0 + 1) * L_IN + r0]     = acc[mt][nt][1] * SCALEF + b1;
                ob[(size_t)o0 * L_IN + r0 + 8]       = acc[mt][nt][2] * SCALEF + b0;
                ob[(size_t)(o0 + 1) * L_IN + r0 + 8] = acc[mt][nt][3] * SCALEF + b1;
            }
        }
    }
}

extern "C" void kernel_launch(void* const* d_in, const int* in_sizes, int n_in,
                              void* d_out, int out_size)
{
    const float* x    = (const float*)d_in[0];
    const float* w    = (const float*)d_in[1];
    const float* bias = (const float*)d_in[2];
    float* out        = (float*)d_out;

    cudaFuncSetAttribute(qconv1d_mma,
                         cudaFuncAttributeMaxDynamicSharedMemorySize, SM_TOTAL);
    qconv1d_mma<<<GRID, THREADS, SM_TOTAL>>>(x, w, bias, out);
}